// round 11
// baseline (speedup 1.0000x reference)
#include <cuda_runtime.h>
#include <cuda_bf16.h>

// Problem constants (from reference): B=64, N=512, T=2048.
// Data ranges: mel_lens in [1024, 2048], seq_lens in [256, 512].
#define GAL_B 64
#define GAL_N 512
#define GAL_T 2048
#define GAL_ROWS (GAL_B * GAL_N)          // 32768
#define GAL_RPB 8                         // rows per block (8 | 512 -> same b)
#define GAL_BLOCKS (GAL_ROWS / GAL_RPB)   // 4096

// Row stride in 16-byte (4-float) units: 2048 floats = 512 ulonglong2.
#define GAL_ROW_U2 (GAL_T / 4)            // 512

typedef unsigned long long u64;

// Scratch (allocation-free: __device__ globals).
__device__ float        g_gal_partials[GAL_BLOCKS];
__device__ unsigned int g_gal_count = 0;   // reset by last block each launch

// ---- sm_103a packed-f32 helpers -------------------------------------------
__device__ __forceinline__ float ex2a(float x) {
    float r; asm("ex2.approx.f32 %0, %1;" : "=f"(r) : "f"(x)); return r;
}
__device__ __forceinline__ u64 pack2(float lo, float hi) {
    u64 r; asm("mov.b64 %0, {%1, %2};" : "=l"(r) : "f"(lo), "f"(hi)); return r;
}
__device__ __forceinline__ void unpack2(u64 v, float& lo, float& hi) {
    asm("mov.b64 {%0, %1}, %2;" : "=f"(lo), "=f"(hi) : "l"(v));
}
__device__ __forceinline__ u64 mul2(u64 a, u64 b) {
    u64 r; asm("mul.rn.f32x2 %0, %1, %2;" : "=l"(r) : "l"(a), "l"(b)); return r;
}
__device__ __forceinline__ u64 add2(u64 a, u64 b) {
    u64 r; asm("add.rn.f32x2 %0, %1, %2;" : "=l"(r) : "l"(a), "l"(b)); return r;
}
__device__ __forceinline__ u64 fma2(u64 a, u64 b, u64 c) {
    u64 r; asm("fma.rn.f32x2 %0, %1, %2, %3;" : "=l"(r) : "l"(a), "l"(b), "l"(c)); return r;
}

// ---------------------------------------------------------------------------
// 4096 blocks x 256 threads; block handles 8 consecutive rows (same batch b).
// Thread tid owns t in [4*tid, 4*tid+4) (chunk A: always live, mel_lens>=1024)
// and [1024+4*tid, ...+4) (chunk B: masked at the end).
//
// Weight: w = 1 - exp2(-u^2), u = n*(s/sl) - t*(s/ml), s = sqrt(log2e/(2g^2)).
// Per-(thread,t) Gaussian recurrence across the 8 rows (u steps by d = s/sl):
//     e <- e * r,  r <- r * c,   c = exp2(-2 d^2)
// Loop body is pure packed f32x2 add/mul/fma. sum(w*A) = sum(A) - sum(e*A);
// B-chunk boundary mask is row-invariant -> applied once at the end.
//
// Fast path front-batches ALL 16 LDG.128 (8 A-rows + 8 B-rows) before any
// compute (launch_bounds(256,2) gives the 128-reg budget this needs), so
// ~131 KB/SM is in flight vs the ~25 KB Little's-law requirement.
// Last-finishing block does the final deterministic double reduction.
// ---------------------------------------------------------------------------
__global__ void __launch_bounds__(256, 2)
gal_main_kernel(const float* __restrict__ A,
                const float* __restrict__ g_ptr,
                const int*   __restrict__ mel_lens,
                const int*   __restrict__ seq_lens,
                float*       __restrict__ out)
{
    const int tid  = threadIdx.x;
    const int row0 = blockIdx.x * GAL_RPB;
    const int b    = row0 >> 9;            // N = 512
    const int n0   = row0 & (GAL_N - 1);

    const int   sl = seq_lens[b];
    const int   ml = mel_lens[b];
    const float g  = *g_ptr;

    const float s      = sqrtf(1.4426950408889634f / (2.0f * g * g));
    const float xscale = s / (float)sl;    // u row-step d
    const float tscale = s / (float)ml;

    const int  tA   = tid * 4;             // < 1024 <= ml : always live
    const int  tB   = 1024 + tid * 4;
    const bool anyB = (tB < ml);

    float sum = 0.0f;

    if (n0 + GAL_RPB <= sl) {
        // ================= fast path: all 8 rows live =================
        const ulonglong2* __restrict__ pA =
            (const ulonglong2*)(A + ((size_t)row0 << 11)) + tid;
        const ulonglong2* __restrict__ pB = pA + 256;   // +1024 floats

        // ---- front-batch ALL loads: 8 A-rows + 8 B-rows ----
        ulonglong2 va[GAL_RPB], vb[GAL_RPB];
        #pragma unroll
        for (int r = 0; r < GAL_RPB; ++r)
            va[r] = pA[r * GAL_ROW_U2];
        if (anyB) {
            #pragma unroll
            for (int r = 0; r < GAL_RPB; ++r)
                vb[r] = pB[r * GAL_ROW_U2];
        }

        // ---- chain init (overlaps with loads in flight) ----
        const float dx  = xscale;
        const float cc  = ex2a(-2.0f * dx * dx);
        const u64   c2  = pack2(cc, cc);
        const float n0f = (float)n0;

        u64 eA[2], rA[2], eB[2], rB[2];
        #pragma unroll
        for (int p = 0; p < 2; ++p) {
            float u0 = n0f * xscale - (float)(tA + 2*p    ) * tscale;
            float u1 = n0f * xscale - (float)(tA + 2*p + 1) * tscale;
            eA[p] = pack2(ex2a(-u0 * u0), ex2a(-u1 * u1));
            rA[p] = pack2(ex2a(fmaf(-2.0f * dx, u0, -dx * dx)),
                          ex2a(fmaf(-2.0f * dx, u1, -dx * dx)));
            float v0 = n0f * xscale - (float)(tB + 2*p    ) * tscale;
            float v1 = n0f * xscale - (float)(tB + 2*p + 1) * tscale;
            eB[p] = pack2(ex2a(-v0 * v0), ex2a(-v1 * v1));
            rB[p] = pack2(ex2a(fmaf(-2.0f * dx, v0, -dx * dx)),
                          ex2a(fmaf(-2.0f * dx, v1, -dx * dx)));
        }

        u64 accRA = 0ull, accEA = 0ull;
        u64 accRB[2] = {0ull, 0ull}, accEB[2] = {0ull, 0ull};

        // ---- chunk A compute (8 rows) ----
        #pragma unroll
        for (int r = 0; r < GAL_RPB; ++r) {
            accRA = add2(accRA, va[r].x);
            accRA = add2(accRA, va[r].y);
            accEA = fma2(eA[0], va[r].x, accEA);
            accEA = fma2(eA[1], va[r].y, accEA);
            eA[0] = mul2(eA[0], rA[0]);  rA[0] = mul2(rA[0], c2);
            eA[1] = mul2(eA[1], rA[1]);  rA[1] = mul2(rA[1], c2);
        }

        // ---- chunk B compute (8 rows) ----
        if (anyB) {
            #pragma unroll
            for (int r = 0; r < GAL_RPB; ++r) {
                accRB[0] = add2(accRB[0], vb[r].x);
                accRB[1] = add2(accRB[1], vb[r].y);
                accEB[0] = fma2(eB[0], vb[r].x, accEB[0]);
                accEB[1] = fma2(eB[1], vb[r].y, accEB[1]);
                eB[0] = mul2(eB[0], rB[0]);  rB[0] = mul2(rB[0], c2);
                eB[1] = mul2(eB[1], rB[1]);  rB[1] = mul2(rB[1], c2);
            }
        }

        float lo, hi;
        unpack2(accRA, lo, hi);  float rawA = lo + hi;
        unpack2(accEA, lo, hi);  float expA = lo + hi;
        sum = rawA - expA;

        if (anyB) {   // per-k boundary mask, row-invariant -> applied once
            float b0, b1, b2, b3, e0, e1, e2, e3;
            unpack2(accRB[0], b0, b1);  unpack2(accRB[1], b2, b3);
            unpack2(accEB[0], e0, e1);  unpack2(accEB[1], e2, e3);
            if (tB + 0 < ml) sum += b0 - e0;
            if (tB + 1 < ml) sum += b1 - e1;
            if (tB + 2 < ml) sum += b2 - e2;
            if (tB + 3 < ml) sum += b3 - e3;
        }
    } else if (n0 < sl) {
        // ================= tail path: 1..7 live rows (rare) =================
        float tsA[4], tsB[4], mB[4];
        #pragma unroll
        for (int k = 0; k < 4; ++k) {
            tsA[k] = (float)(tA + k) * tscale;
            tsB[k] = (float)(tB + k) * tscale;
            mB[k]  = (tB + k < ml) ? 1.0f : 0.0f;
        }
        const int live = sl - n0;
        const float4* __restrict__ base = (const float4*)(A + ((size_t)row0 << 11));
        for (int r = 0; r < live; ++r) {
            const float xs = (float)(n0 + r) * xscale;
            const float4* __restrict__ Arow = base + r * (GAL_T / 4);
            {
                const float4 a = Arow[tid];
                const float av[4] = {a.x, a.y, a.z, a.w};
                #pragma unroll
                for (int k = 0; k < 4; ++k) {
                    const float u = xs - tsA[k];
                    sum = fmaf(1.0f - ex2a(-u * u), av[k], sum);
                }
            }
            if (anyB) {
                const float4 a = Arow[tid + 256];
                const float av[4] = {a.x, a.y, a.z, a.w};
                #pragma unroll
                for (int k = 0; k < 4; ++k) {
                    const float u = xs - tsB[k];
                    sum = fmaf((1.0f - ex2a(-u * u)) * mB[k], av[k], sum);
                }
            }
        }
    }
    // (blocks with n0 >= sl fall through with sum = 0)

    // ---- block reduction (deterministic) ----
    #pragma unroll
    for (int o = 16; o > 0; o >>= 1)
        sum += __shfl_xor_sync(0xffffffffu, sum, o);

    __shared__ float warp_sums[8];
    if ((tid & 31) == 0) warp_sums[tid >> 5] = sum;
    __syncthreads();

    __shared__ bool is_last;
    if (tid == 0) {
        float v = warp_sums[0];
        #pragma unroll
        for (int w = 1; w < 8; ++w) v += warp_sums[w];
        g_gal_partials[blockIdx.x] = v;
        __threadfence();                                  // publish partial
        unsigned int old = atomicAdd(&g_gal_count, 1u);
        is_last = (old == GAL_BLOCKS - 1);
    }
    __syncthreads();

    // ---- last block: final deterministic reduction in double ----
    if (is_last) {
        __threadfence();                                  // acquire partials
        const float4* __restrict__ p4 = (const float4*)g_gal_partials;
        double sd = 0.0;
        #pragma unroll
        for (int j = 0; j < GAL_BLOCKS / 4 / 256; ++j) {  // 4 float4 each
            const float4 p = p4[tid + j * 256];
            sd += ((double)p.x + (double)p.y) + ((double)p.z + (double)p.w);
        }
        __shared__ double sh[256];
        sh[tid] = sd;
        __syncthreads();
        #pragma unroll
        for (int stride = 128; stride > 0; stride >>= 1) {
            if (tid < stride) sh[tid] += sh[tid + stride];
            __syncthreads();
        }
        if (tid == 0) {
            *out = (float)(sh[0] / (double)GAL_B);
            g_gal_count = 0;                              // reset for replay
        }
    }
}

// ---------------------------------------------------------------------------
// kernel_launch: inputs per metadata order:
//   d_in[0] = A        float32  [B*N*T]
//   d_in[1] = g        float32  [1]
//   d_in[2] = mel_lens int32    [B]
//   d_in[3] = seq_lens int32    [B]
// d_out: float32 [1]
// ---------------------------------------------------------------------------
extern "C" void kernel_launch(void* const* d_in, const int* in_sizes, int n_in,
                              void* d_out, int out_size)
{
    const float* A        = (const float*)d_in[0];
    const float* g        = (const float*)d_in[1];
    const int*   mel_lens = (const int*)d_in[2];
    const int*   seq_lens = (const int*)d_in[3];
    float*       out      = (float*)d_out;

    gal_main_kernel<<<GAL_BLOCKS, 256>>>(A, g, mel_lens, seq_lens, out);
}

// round 12
// speedup vs baseline: 1.3779x; 1.3779x over previous
#include <cuda_runtime.h>
#include <cuda_bf16.h>

// Problem constants (from reference): B=64, N=512, T=2048.
// Data ranges: mel_lens in [1024, 2048], seq_lens in [256, 512].
#define GAL_B 64
#define GAL_N 512
#define GAL_T 2048
#define GAL_ROWS (GAL_B * GAL_N)          // 32768
#define GAL_RPB 32                        // rows per block (32 | 512 -> same b)
#define GAL_BLOCKS (GAL_ROWS / GAL_RPB)   // 1024
#define GAL_GRP 4                         // rows per pipeline group

// Row stride in 16-byte (4-float) units: 2048 floats = 512 ulonglong2.
#define GAL_ROW_U2 (GAL_T / 4)            // 512

typedef unsigned long long u64;

// Scratch (allocation-free: __device__ globals).
__device__ float        g_gal_partials[GAL_BLOCKS];
__device__ unsigned int g_gal_count = 0;   // reset by last block each launch

// ---- sm_103a packed-f32 helpers -------------------------------------------
__device__ __forceinline__ float ex2a(float x) {
    float r; asm("ex2.approx.f32 %0, %1;" : "=f"(r) : "f"(x)); return r;
}
__device__ __forceinline__ u64 pack2(float lo, float hi) {
    u64 r; asm("mov.b64 %0, {%1, %2};" : "=l"(r) : "f"(lo), "f"(hi)); return r;
}
__device__ __forceinline__ void unpack2(u64 v, float& lo, float& hi) {
    asm("mov.b64 {%0, %1}, %2;" : "=f"(lo), "=f"(hi) : "l"(v));
}
__device__ __forceinline__ u64 mul2(u64 a, u64 b) {
    u64 r; asm("mul.rn.f32x2 %0, %1, %2;" : "=l"(r) : "l"(a), "l"(b)); return r;
}
__device__ __forceinline__ u64 add2(u64 a, u64 b) {
    u64 r; asm("add.rn.f32x2 %0, %1, %2;" : "=l"(r) : "l"(a), "l"(b)); return r;
}
__device__ __forceinline__ u64 fma2(u64 a, u64 b, u64 c) {
    u64 r; asm("fma.rn.f32x2 %0, %1, %2, %3;" : "=l"(r) : "l"(a), "l"(b), "l"(c)); return r;
}

// ---------------------------------------------------------------------------
// 1024 blocks x 256 threads; block handles 32 consecutive rows (same batch b)
// as a software pipeline over 8 groups of 4 rows:
//    compute A(g) -> issue A(g+1) loads -> compute B(g) -> issue B(g+1) loads
// so 4-8 LDG.128 per warp stay in flight CONTINUOUSLY (vs R10's one-shot
// burst-then-drain, which idled DRAM during compute).
//
// Thread tid owns t in [4*tid,4*tid+4) (chunk A: always live, mel_lens>=1024)
// and [1024+4*tid,...+4) (chunk B: masked). Weight w = 1 - exp2(-u^2),
// u = n*(s/sl) - t*(s/ml), s = sqrt(log2e/(2g^2)); Gaussian recurrence in n:
//    e <- e*r, r <- r*c, c = exp2(-2 d^2), d = s/sl
// rolls across all 32 rows (one chain init per block). The B boundary mask
// is PREMULTIPLIED into the eB chain init (multiplicative updates preserve
// the 0/1 factor) and applied to raw-B via fma2(mask,...), so A and B share
// ONE raw and ONE exp accumulator (register diet for 3 CTAs/SM).
// Last-finishing block does the final deterministic double reduction.
// ---------------------------------------------------------------------------
__global__ void __launch_bounds__(256, 3)
gal_main_kernel(const float* __restrict__ A,
                const float* __restrict__ g_ptr,
                const int*   __restrict__ mel_lens,
                const int*   __restrict__ seq_lens,
                float*       __restrict__ out)
{
    const int tid  = threadIdx.x;
    const int row0 = blockIdx.x * GAL_RPB;
    const int b    = row0 >> 9;            // N = 512
    const int n0   = row0 & (GAL_N - 1);

    const int   sl = seq_lens[b];
    const int   ml = mel_lens[b];
    const float g  = *g_ptr;

    const float s      = sqrtf(1.4426950408889634f / (2.0f * g * g));
    const float xscale = s / (float)sl;    // u row-step d
    const float tscale = s / (float)ml;

    const int  tA   = tid * 4;             // < 1024 <= ml : always live
    const int  tB   = 1024 + tid * 4;
    const bool anyB = (tB < ml);

    float sum = 0.0f;

    const int Lraw = sl - n0;
    const int L    = (Lraw > GAL_RPB) ? GAL_RPB : Lraw;   // live rows, may be <=0
    const int G    = (L > 0) ? (L >> 2) : 0;              // full 4-row groups

    if (G > 0) {
        // ---- chain init at n = n0 (masks premultiplied into eB) ----
        const float dx  = xscale;
        const float cc  = ex2a(-2.0f * dx * dx);
        const u64   c2  = pack2(cc, cc);
        const float n0f = (float)n0;

        float mk[4];
        #pragma unroll
        for (int k = 0; k < 4; ++k) mk[k] = (tB + k < ml) ? 1.0f : 0.0f;
        const u64 mB01 = pack2(mk[0], mk[1]);
        const u64 mB23 = pack2(mk[2], mk[3]);

        u64 eA[2], rA[2], eB[2], rB[2];
        #pragma unroll
        for (int p = 0; p < 2; ++p) {
            float u0 = n0f * xscale - (float)(tA + 2*p    ) * tscale;
            float u1 = n0f * xscale - (float)(tA + 2*p + 1) * tscale;
            eA[p] = pack2(ex2a(-u0 * u0), ex2a(-u1 * u1));
            rA[p] = pack2(ex2a(fmaf(-2.0f * dx, u0, -dx * dx)),
                          ex2a(fmaf(-2.0f * dx, u1, -dx * dx)));
            float v0 = n0f * xscale - (float)(tB + 2*p    ) * tscale;
            float v1 = n0f * xscale - (float)(tB + 2*p + 1) * tscale;
            eB[p] = pack2(mk[2*p]   * ex2a(-v0 * v0),
                          mk[2*p+1] * ex2a(-v1 * v1));
            rB[p] = pack2(ex2a(fmaf(-2.0f * dx, v0, -dx * dx)),
                          ex2a(fmaf(-2.0f * dx, v1, -dx * dx)));
        }

        u64 accR = 0ull, accE = 0ull;      // (0.0f, 0.0f) packed

        const ulonglong2* __restrict__ pA =
            (const ulonglong2*)(A + ((size_t)row0 << 11)) + tid;

        // ---- prologue: load group 0 ----
        ulonglong2 va[GAL_GRP], vb[GAL_GRP];
        #pragma unroll
        for (int r = 0; r < GAL_GRP; ++r) va[r] = pA[r * GAL_ROW_U2];
        if (anyB) {
            #pragma unroll
            for (int r = 0; r < GAL_GRP; ++r) vb[r] = pA[r * GAL_ROW_U2 + 256];
        }

        // ---- steady-state pipeline over G groups ----
        int gi = 0;
        for (;;) {
            const bool more = (gi + 1 < G);

            // compute A(gi); vb(gi) already in flight
            #pragma unroll
            for (int r = 0; r < GAL_GRP; ++r) {
                accR  = add2(accR, va[r].x);
                accR  = add2(accR, va[r].y);
                accE  = fma2(eA[0], va[r].x, accE);
                accE  = fma2(eA[1], va[r].y, accE);
                eA[0] = mul2(eA[0], rA[0]);  rA[0] = mul2(rA[0], c2);
                eA[1] = mul2(eA[1], rA[1]);  rA[1] = mul2(rA[1], c2);
            }

            // issue A(gi+1) into the just-consumed buffer
            if (more) {
                #pragma unroll
                for (int r = 0; r < GAL_GRP; ++r)
                    va[r] = pA[(r + GAL_GRP) * GAL_ROW_U2];
            }

            // compute B(gi); va(gi+1) in flight
            if (anyB) {
                #pragma unroll
                for (int r = 0; r < GAL_GRP; ++r) {
                    accR  = fma2(mB01, vb[r].x, accR);
                    accR  = fma2(mB23, vb[r].y, accR);
                    accE  = fma2(eB[0], vb[r].x, accE);
                    accE  = fma2(eB[1], vb[r].y, accE);
                    eB[0] = mul2(eB[0], rB[0]);  rB[0] = mul2(rB[0], c2);
                    eB[1] = mul2(eB[1], rB[1]);  rB[1] = mul2(rB[1], c2);
                }
                if (more) {
                    #pragma unroll
                    for (int r = 0; r < GAL_GRP; ++r)
                        vb[r] = pA[(r + GAL_GRP) * GAL_ROW_U2 + 256];
                }
            }

            if (!more) break;
            pA += GAL_GRP * GAL_ROW_U2;
            ++gi;
        }

        float lo, hi;
        unpack2(accR, lo, hi);  sum  = lo + hi;
        unpack2(accE, lo, hi);  sum -= lo + hi;
    }

    // ---- scalar tail: rows 4G .. L-1 (0..3 rows; boundary blocks only) ----
    if (L > 4 * G) {
        float tsA[4], tsB[4], mB[4];
        #pragma unroll
        for (int k = 0; k < 4; ++k) {
            tsA[k] = (float)(tA + k) * tscale;
            tsB[k] = (float)(tB + k) * tscale;
            mB[k]  = (tB + k < ml) ? 1.0f : 0.0f;
        }
        const float4* __restrict__ base = (const float4*)(A + ((size_t)row0 << 11));
        for (int r = 4 * G; r < L; ++r) {
            const float xs = (float)(n0 + r) * xscale;
            const float4* __restrict__ Arow = base + r * (GAL_T / 4);
            {
                const float4 a = Arow[tid];
                const float av[4] = {a.x, a.y, a.z, a.w};
                #pragma unroll
                for (int k = 0; k < 4; ++k) {
                    const float u = xs - tsA[k];
                    sum = fmaf(1.0f - ex2a(-u * u), av[k], sum);
                }
            }
            if (anyB) {
                const float4 a = Arow[tid + 256];
                const float av[4] = {a.x, a.y, a.z, a.w};
                #pragma unroll
                for (int k = 0; k < 4; ++k) {
                    const float u = xs - tsB[k];
                    sum = fmaf((1.0f - ex2a(-u * u)) * mB[k], av[k], sum);
                }
            }
        }
    }
    // (blocks with n0 >= sl fall through with sum = 0)

    // ---- block reduction (deterministic) ----
    #pragma unroll
    for (int o = 16; o > 0; o >>= 1)
        sum += __shfl_xor_sync(0xffffffffu, sum, o);

    __shared__ float warp_sums[8];
    if ((tid & 31) == 0) warp_sums[tid >> 5] = sum;
    __syncthreads();

    __shared__ bool is_last;
    if (tid == 0) {
        float v = warp_sums[0];
        #pragma unroll
        for (int w = 1; w < 8; ++w) v += warp_sums[w];
        g_gal_partials[blockIdx.x] = v;
        __threadfence();                                  // publish partial
        unsigned int old = atomicAdd(&g_gal_count, 1u);
        is_last = (old == GAL_BLOCKS - 1);
    }
    __syncthreads();

    // ---- last block: final deterministic reduction in double ----
    if (is_last) {
        __threadfence();                                  // acquire partials
        const float4* __restrict__ p4 = (const float4*)g_gal_partials;
        double sd = 0.0;
        #pragma unroll
        for (int j = 0; j < GAL_BLOCKS / 4 / 256; ++j) {  // 1 float4 each
            const float4 p = p4[tid + j * 256];
            sd += ((double)p.x + (double)p.y) + ((double)p.z + (double)p.w);
        }
        __shared__ double sh[256];
        sh[tid] = sd;
        __syncthreads();
        #pragma unroll
        for (int stride = 128; stride > 0; stride >>= 1) {
            if (tid < stride) sh[tid] += sh[tid + stride];
            __syncthreads();
        }
        if (tid == 0) {
            *out = (float)(sh[0] / (double)GAL_B);
            g_gal_count = 0;                              // reset for replay
        }
    }
}

// ---------------------------------------------------------------------------
// kernel_launch: inputs per metadata order:
//   d_in[0] = A        float32  [B*N*T]
//   d_in[1] = g        float32  [1]
//   d_in[2] = mel_lens int32    [B]
//   d_in[3] = seq_lens int32    [B]
// d_out: float32 [1]
// ---------------------------------------------------------------------------
extern "C" void kernel_launch(void* const* d_in, const int* in_sizes, int n_in,
                              void* d_out, int out_size)
{
    const float* A        = (const float*)d_in[0];
    const float* g        = (const float*)d_in[1];
    const int*   mel_lens = (const int*)d_in[2];
    const int*   seq_lens = (const int*)d_in[3];
    float*       out      = (float*)d_out;

    gal_main_kernel<<<GAL_BLOCKS, 256>>>(A, g, mel_lens, seq_lens, out);
}